// round 15
// baseline (speedup 1.0000x reference)
#include <cuda_runtime.h>
#include <cstdint>

#define BATCH   4
#define NPTS    32768
#define NQ      2048
#define KNN     16
#define QSTRIDE (NPTS / NQ)      // 16
#define TILE    2048
#define WARPS   4
#define NTHREADS (WARPS * 32)
#define QPW     2                // queries per warp
#define FULLMASK 0xffffffffu

#define MUL_F32X2(out, a, b) \
    asm("mul.rn.f32x2 %0, %1, %2;" : "=l"(out) : "l"(a), "l"(b))
#define ADD_F32X2(out, a, b) \
    asm("add.rn.f32x2 %0, %1, %2;" : "=l"(out) : "l"(a), "l"(b))
#define PACK_F32X2(out, lo, hi) \
    asm("mov.b64 %0, {%1, %2};" : "=l"(out) : "r"(lo), "r"(hi))
#define UNPACK_F32X2(lo, hi, in) \
    asm("mov.b64 {%0, %1}, %2;" : "=r"(lo), "=r"(hi) : "l"(in))

// Insert balloted candidates (lowest lane first) into the warp-distributed
// sorted top-16 (lane l < 16 holds the l-th smallest). Candidate index for
// lane src is baseIdx + 4*src (4-consecutive-points-per-lane mapping).
__device__ __forceinline__ void warp_insert(unsigned hits, float d, int baseIdx,
                                            float& list_d, unsigned& list_i,
                                            float& kth, int lane)
{
    while (hits) {
        const int src = __ffs(hits) - 1;
        hits &= hits - 1;
        const float dv = __shfl_sync(FULLMASK, d, src);   // warp-uniform
        if (dv < kth) {                                   // kth may have tightened
            const unsigned bal = __ballot_sync(FULLMASK, dv < list_d);
            const int pos = __ffs(bal) - 1;               // insert after ties
            const float    pd = __shfl_up_sync(FULLMASK, list_d, 1);
            const unsigned pi = __shfl_up_sync(FULLMASK, list_i, 1);
            if (lane > pos)       { list_d = pd; list_i = pi; }
            else if (lane == pos) { list_d = dv; list_i = (unsigned)(baseIdx + 4 * src); }
            kth = __shfl_sync(FULLMASK, list_d, 15);
        }
    }
}

__global__ __launch_bounds__(NTHREADS)
void knn_kernel(const float* __restrict__ xyz,
                float* __restrict__ out)      // f32: [idx 131072][pts 24576]
{
    __shared__ __align__(16) float s[TILE * 3];

    const int lane = threadIdx.x & 31;
    const int warp = threadIdx.x >> 5;
    const int qPerBlock = WARPS * QPW;                   // 8
    const int blocksPerBatch = NQ / qPerBlock;           // 256
    const int b  = blockIdx.x / blocksPerBatch;
    const int q0 = (blockIdx.x % blocksPerBatch) * qPerBlock + warp * QPW;
    const int q1 = q0 + 1;

    const float* base = xyz + (size_t)b * NPTS * 3;

    const float q0x = base[q0 * QSTRIDE * 3 + 0];
    const float q0y = base[q0 * QSTRIDE * 3 + 1];
    const float q0z = base[q0 * QSTRIDE * 3 + 2];
    const float q1x = base[q1 * QSTRIDE * 3 + 0];
    const float q1y = base[q1 * QSTRIDE * 3 + 1];
    const float q1z = base[q1 * QSTRIDE * 3 + 2];

    const float FINF = __int_as_float(0x7f800000);

    float    l0d = FINF, l1d = FINF;
    unsigned l0i = 0xffffffffu, l1i = 0xffffffffu;
    float    kth0 = FINF, kth1 = FINF;

#pragma unroll 1
    for (int t = 0; t < NPTS / TILE; t++) {
        __syncthreads();
        {   // cooperative tile load, float4-vectorized & coalesced
            const float4* g  = (const float4*)(base + (size_t)t * TILE * 3);
            float4*       sv = (float4*)s;
#pragma unroll 1
            for (int i = threadIdx.x; i < TILE * 3 / 4; i += NTHREADS)
                sv[i] = g[i];
        }
        __syncthreads();

#pragma unroll 4
        for (int jj = 0; jj < TILE; jj += 128) {
            // lane owns 4 consecutive points -> their 12 floats are exactly
            // three aligned float4s: 3 LDS.128 per 128 points (was 12 LDS).
            const int    j0 = jj + lane * 4;
            const float4 A  = *(const float4*)(s + 3 * j0);
            const float4 B  = *(const float4*)(s + 3 * j0 + 4);
            const float4 C  = *(const float4*)(s + 3 * j0 + 8);

            const float px[4] = {A.x, A.w, B.z, C.y};
            const float py[4] = {A.y, B.x, B.w, C.z};
            const float pz[4] = {A.z, B.y, C.x, C.w};

            float d0[4], d1[4];
#pragma unroll
            for (int u = 0; u < 4; u++) {
                // Scalar subs, packed f32x2 mul/add (per-half IEEE rn ==
                // scalar): bit-exact vs XLA's (dx*dx+dy*dy)+dz*dz, no FMA.
                const float dx0 = __fsub_rn(q0x, px[u]), dx1 = __fsub_rn(q1x, px[u]);
                const float dy0 = __fsub_rn(q0y, py[u]), dy1 = __fsub_rn(q1y, py[u]);
                const float dz0 = __fsub_rn(q0z, pz[u]), dz1 = __fsub_rn(q1z, pz[u]);
                uint64_t vx, vy, vz, sx, sy, sz, sxy, sd;
                PACK_F32X2(vx, __float_as_uint(dx0), __float_as_uint(dx1));
                PACK_F32X2(vy, __float_as_uint(dy0), __float_as_uint(dy1));
                PACK_F32X2(vz, __float_as_uint(dz0), __float_as_uint(dz1));
                MUL_F32X2(sx, vx, vx);
                MUL_F32X2(sy, vy, vy);
                MUL_F32X2(sz, vz, vz);
                ADD_F32X2(sxy, sx, sy);
                ADD_F32X2(sd, sxy, sz);
                unsigned u0, u1;
                UNPACK_F32X2(u0, u1, sd);
                d0[u] = __uint_as_float(u0);
                d1[u] = __uint_as_float(u1);
            }

            // cheap gate: min over the 4 candidates per query
            const float m0 = fminf(fminf(d0[0], d0[1]), fminf(d0[2], d0[3]));
            const float m1 = fminf(fminf(d1[0], d1[1]), fminf(d1[2], d1[3]));
            const bool  p0 = m0 < kth0;
            const bool  p1 = m1 < kth1;

            if (__ballot_sync(FULLMASK, p0 | p1)) {       // warp-uniform, rare
                const int gbase = t * TILE + jj;          // GLOBAL tile offset
#pragma unroll
                for (int u = 0; u < 4; u++) {
                    const unsigned h0 = __ballot_sync(FULLMASK, d0[u] < kth0);
                    if (h0) warp_insert(h0, d0[u], gbase + u, l0d, l0i, kth0, lane);
                    const unsigned h1 = __ballot_sync(FULLMASK, d1[u] < kth1);
                    if (h1) warp_insert(h1, d1[u], gbase + u, l1d, l1i, kth1, lane);
                }
            }
        }
    }

    // Epilogue: lists are already the sorted warp-global top-16s.
    const size_t qg0 = (size_t)b * NQ + q0;
    const size_t qg1 = (size_t)b * NQ + q1;
    if (lane < KNN) {
        out[qg0 * KNN + lane] = (float)l0i;     // exact for < 2^24
        out[qg1 * KNN + lane] = (float)l1i;
    }
    if (lane == 0) {
        float* op0 = out + (size_t)BATCH * NQ * KNN + qg0 * 3;
        float* op1 = out + (size_t)BATCH * NQ * KNN + qg1 * 3;
        op0[0] = q0x; op0[1] = q0y; op0[2] = q0z;
        op1[0] = q1x; op1[1] = q1y; op1[2] = q1z;
    }
}

extern "C" void kernel_launch(void* const* d_in, const int* in_sizes, int n_in,
                              void* d_out, int out_size)
{
    // select xyz by element count (4*32768*3), fallback: largest input
    int xi = 0, best = -1;
    for (int i = 0; i < n_in; i++) {
        if (in_sizes[i] == BATCH * NPTS * 3) { xi = i; best = 0x7fffffff; break; }
        if (in_sizes[i] > best) { best = in_sizes[i]; xi = i; }
    }
    const float* xyz = (const float*)d_in[xi];
    (void)out_size;

    knn_kernel<<<BATCH * NQ / (WARPS * QPW), NTHREADS>>>(xyz, (float*)d_out);
}